// round 2
// baseline (speedup 1.0000x reference)
#include <cuda_runtime.h>
#include <cstdint>

#define Bz   16
#define Sz   4096
#define Dz   768
#define Hh   12
#define HD   64
#define E3   2304          // 3*Dz
#define Mrow (Bz*Sz)       // 65536
#define NC   4             // S-chunks for kv partial
#define CS   (Sz/NC)       // 1024

// -------- scratch (device globals: allocation-free) --------
__device__ float g_qkv[(size_t)Mrow * E3];        // [m, e] e = n*768 + h*64 + dd
__device__ float g_mid[(size_t)Mrow * Dz];        // pre-projection activations
__device__ float g_kvp[(size_t)Bz * Hh * NC * HD * HD];
__device__ float g_kv [(size_t)Bz * Hh * HD * HD]; // (1/pi) * k_hat^T v, [dd][ee]

__device__ __forceinline__ float warp_sum(float v) {
    v += __shfl_xor_sync(0xffffffffu, v, 16);
    v += __shfl_xor_sync(0xffffffffu, v, 8);
    v += __shfl_xor_sync(0xffffffffu, v, 4);
    v += __shfl_xor_sync(0xffffffffu, v, 2);
    v += __shfl_xor_sync(0xffffffffu, v, 1);
    return v;
}

// ============================================================
// SGEMM: C[m,n] = sum_k A[m,k]*W[n,k] + bias[n]
// A: [Mdim,Kdim] row-major, W: [Ndim,Kdim] row-major.
// 128x128 block tile, 8x8 per thread, BK=8, 256 threads.
// ============================================================
__global__ __launch_bounds__(256, 2)
void sgemm_bias(const float* __restrict__ A, const float* __restrict__ W,
                const float* __restrict__ bias, float* __restrict__ C,
                int Ndim, int Kdim) {
    __shared__ float As[8][128];
    __shared__ float Ws[8][128];
    const int tid  = threadIdx.x;
    const int m0   = blockIdx.y * 128;
    const int n0   = blockIdx.x * 128;
    const int rowL = tid >> 1;            // 0..127
    const int colL = (tid & 1) << 2;      // 0 or 4
    const int tr   = (tid >> 4) << 3;     // 0..120 step 8 (m)
    const int tc   = (tid & 15) << 3;     // 0..120 step 8 (n)

    const float* Ap = A + (size_t)(m0 + rowL) * Kdim + colL;
    const float* Wp = W + (size_t)(n0 + rowL) * Kdim + colL;

    float acc[8][8];
    #pragma unroll
    for (int i = 0; i < 8; i++)
        #pragma unroll
        for (int j = 0; j < 8; j++) acc[i][j] = 0.f;

    for (int k0 = 0; k0 < Kdim; k0 += 8) {
        float4 a4 = *(const float4*)(Ap + k0);
        float4 w4 = *(const float4*)(Wp + k0);
        As[colL+0][rowL] = a4.x; As[colL+1][rowL] = a4.y;
        As[colL+2][rowL] = a4.z; As[colL+3][rowL] = a4.w;
        Ws[colL+0][rowL] = w4.x; Ws[colL+1][rowL] = w4.y;
        Ws[colL+2][rowL] = w4.z; Ws[colL+3][rowL] = w4.w;
        __syncthreads();
        #pragma unroll
        for (int k = 0; k < 8; k++) {
            float rm[8], rn[8];
            *(float4*)(rm)     = *(const float4*)&As[k][tr];
            *(float4*)(rm + 4) = *(const float4*)&As[k][tr + 4];
            *(float4*)(rn)     = *(const float4*)&Ws[k][tc];
            *(float4*)(rn + 4) = *(const float4*)&Ws[k][tc + 4];
            #pragma unroll
            for (int i = 0; i < 8; i++)
                #pragma unroll
                for (int j = 0; j < 8; j++)
                    acc[i][j] += rm[i] * rn[j];
        }
        __syncthreads();
    }

    float4 bv0 = *(const float4*)&bias[n0 + tc];
    float4 bv1 = *(const float4*)&bias[n0 + tc + 4];
    #pragma unroll
    for (int i = 0; i < 8; i++) {
        size_t row = (size_t)(m0 + tr + i) * Ndim + n0 + tc;
        float4 o0 = make_float4(acc[i][0] + bv0.x, acc[i][1] + bv0.y,
                                acc[i][2] + bv0.z, acc[i][3] + bv0.w);
        float4 o1 = make_float4(acc[i][4] + bv1.x, acc[i][5] + bv1.y,
                                acc[i][6] + bv1.z, acc[i][7] + bv1.w);
        *(float4*)&C[row]     = o0;
        *(float4*)&C[row + 4] = o1;
    }
}

// ============================================================
// kv partials: for (b,h,chunk): acc[dd][ee] = sum_{s in chunk} khat[s,dd]*v[s,ee]
// ============================================================
__global__ __launch_bounds__(256)
void kv_partial(float* __restrict__ kvp) {
    const int bh    = blockIdx.x;          // 0..191
    const int chunk = blockIdx.y;          // 0..3
    const int b = bh / Hh, h = bh % Hh;
    __shared__ float kh[8][64];
    __shared__ float vr[8][64];
    const int tid  = threadIdx.x;
    const int w    = tid >> 5, lane = tid & 31;
    const int tr4  = (tid >> 4) * 4;       // dd base
    const int tc4  = (tid & 15) * 4;       // ee base

    float acc[4][4];
    #pragma unroll
    for (int i = 0; i < 4; i++)
        #pragma unroll
        for (int j = 0; j < 4; j++) acc[i][j] = 0.f;

    for (int t = 0; t < CS / 8; t++) {
        const int s = chunk * CS + t * 8 + w;
        const size_t base = (size_t)(b * Sz + s) * E3 + h * HD;
        float k0 = g_qkv[base + Dz + lane];
        float k1 = g_qkv[base + Dz + 32 + lane];
        float v0 = g_qkv[base + 2 * Dz + lane];
        float v1 = g_qkv[base + 2 * Dz + 32 + lane];
        float nk = warp_sum(k0 * k0 + k1 * k1);
        float rk = rsqrtf(nk);
        kh[w][lane]      = k0 * rk;
        kh[w][lane + 32] = k1 * rk;
        vr[w][lane]      = v0;
        vr[w][lane + 32] = v1;
        __syncthreads();
        #pragma unroll
        for (int s8 = 0; s8 < 8; s8++) {
            float4 kk = *(const float4*)&kh[s8][tr4];
            float4 vv = *(const float4*)&vr[s8][tc4];
            const float kkv[4] = {kk.x, kk.y, kk.z, kk.w};
            const float vvv[4] = {vv.x, vv.y, vv.z, vv.w};
            #pragma unroll
            for (int i = 0; i < 4; i++)
                #pragma unroll
                for (int j = 0; j < 4; j++)
                    acc[i][j] += kkv[i] * vvv[j];
        }
        __syncthreads();
    }
    const size_t pbase = ((size_t)bh * NC + chunk) * (HD * HD);
    #pragma unroll
    for (int i = 0; i < 4; i++) {
        float4 o = make_float4(acc[i][0], acc[i][1], acc[i][2], acc[i][3]);
        *(float4*)&kvp[pbase + (size_t)(tr4 + i) * HD + tc4] = o;
    }
}

__global__ void kv_reduce(const float* __restrict__ kvp, float* __restrict__ kv) {
    const int bh = blockIdx.x;
    const float inv_pi = 0.31830988618379067f;
    for (int i = threadIdx.x; i < HD * HD; i += blockDim.x) {
        float s = 0.f;
        #pragma unroll
        for (int c = 0; c < NC; c++)
            s += kvp[((size_t)bh * NC + c) * (HD * HD) + i];
        kv[(size_t)bh * (HD * HD) + i] = s * inv_pi;
    }
}

// ============================================================
// Fused: out = normalize(0.5*v + qhat @ kv) + dconv(v), write to g_mid
// one block = (b, h, 64 s-values); warp handles 8 s.
// ============================================================
__global__ __launch_bounds__(256)
void attn_out(const float* __restrict__ kv, const float* __restrict__ wd) {
    __shared__ float kvs[64 * 64];
    __shared__ float vt[72 * 64];   // rows s0-4 .. s0+67
    __shared__ float qs[8][64];
    __shared__ float wds[9];
    const int b = blockIdx.z, h = blockIdx.y;
    const int s0 = blockIdx.x * 64;
    const int tid = threadIdx.x, w = tid >> 5, lane = tid & 31;
    const int bh = b * Hh + h;

    if (tid < 9) wds[tid] = wd[h * 9 + tid];
    for (int i = tid * 4; i < 64 * 64; i += 1024)
        *(float4*)&kvs[i] = *(const float4*)&kv[(size_t)bh * 4096 + i];
    for (int idx = tid; idx < 72 * 64; idx += 256) {
        const int r = idx >> 6, c = idx & 63;
        const int s = s0 - 4 + r;
        vt[idx] = (s >= 0 && s < Sz)
                ? g_qkv[(size_t)(b * Sz + s) * E3 + 2 * Dz + h * HD + c] : 0.f;
    }
    __syncthreads();

    for (int i = 0; i < 8; i++) {
        const int s = s0 + w * 8 + i;
        const size_t base = (size_t)(b * Sz + s) * E3 + h * HD;
        float2 q2 = *(const float2*)&g_qkv[base + 2 * lane];
        float rq = rsqrtf(warp_sum(q2.x * q2.x + q2.y * q2.y));
        *(float2*)&qs[w][2 * lane] = make_float2(q2.x * rq, q2.y * rq);
        __syncwarp();
        float ax = 0.f, ay = 0.f;
        #pragma unroll 8
        for (int e = 0; e < 64; e++) {
            const float qe = qs[w][e];
            float2 kk = *(const float2*)&kvs[e * 64 + 2 * lane];
            ax += qe * kk.x;
            ay += qe * kk.y;
        }
        __syncwarp();
        const int r = (s - s0) + 4;
        float2 vv = *(const float2*)&vt[r * 64 + 2 * lane];
        float ox = 0.5f * vv.x + ax;   // kv already has 1/pi folded in
        float oy = 0.5f * vv.y + ay;
        float ro = rsqrtf(warp_sum(ox * ox + oy * oy));
        ox *= ro; oy *= ro;
        float dcx = 0.f, dcy = 0.f;
        #pragma unroll
        for (int j = 0; j < 9; j++) {
            float2 vj = *(const float2*)&vt[(s - s0 + j) * 64 + 2 * lane];
            dcx += wds[j] * vj.x;
            dcy += wds[j] * vj.y;
        }
        *(float2*)&g_mid[(size_t)(b * Sz + s) * Dz + h * HD + 2 * lane] =
            make_float2(ox + dcx, oy + dcy);
    }
}

// ============================================================
extern "C" void kernel_launch(void* const* d_in, const int* in_sizes, int n_in,
                              void* d_out, int out_size) {
    const float* x      = (const float*)d_in[0];
    const float* w_qkv  = (const float*)d_in[1];
    const float* b_qkv  = (const float*)d_in[2];
    const float* w_proj = (const float*)d_in[3];
    const float* b_proj = (const float*)d_in[4];
    const float* w_dcv  = (const float*)d_in[5];
    float* out = (float*)d_out;

    void *p_qkv, *p_mid, *p_kvp, *p_kv;
    cudaGetSymbolAddress(&p_qkv, g_qkv);
    cudaGetSymbolAddress(&p_mid, g_mid);
    cudaGetSymbolAddress(&p_kvp, g_kvp);
    cudaGetSymbolAddress(&p_kv,  g_kv);

    // 1) qkv = x @ w_qkv^T + b_qkv
    sgemm_bias<<<dim3(E3 / 128, Mrow / 128), 256>>>(
        x, w_qkv, b_qkv, (float*)p_qkv, E3, Dz);
    // 2) kv partials + reduce (scales by 1/pi)
    kv_partial<<<dim3(Bz * Hh, NC), 256>>>((float*)p_kvp);
    kv_reduce<<<Bz * Hh, 256>>>((const float*)p_kvp, (float*)p_kv);
    // 3) fused attention epilogue -> g_mid
    attn_out<<<dim3(Sz / 64, Hh, Bz), 256>>>((const float*)p_kv, w_dcv);
    // 4) final projection
    sgemm_bias<<<dim3(Dz / 128, Mrow / 128), 256>>>(
        (const float*)p_mid, w_proj, b_proj, out, Dz, Dz);
}

// round 4
// speedup vs baseline: 2.7570x; 2.7570x over previous
#include <cuda_runtime.h>
#include <cstdint>

#define Bz   16
#define Sz   4096
#define Dz   768
#define Hh   12
#define HD   64
#define E3   2304          // 3*Dz
#define Mrow (Bz*Sz)       // 65536
#define NC   4             // S-chunks for kv partial
#define CS   (Sz/NC)       // 1024

// -------- scratch (device globals: allocation-free) --------
__device__ float g_qkv[(size_t)Mrow * E3];        // [m, e] e = n*768 + h*64 + dd
__device__ float g_mid[(size_t)Mrow * Dz];        // pre-projection activations
__device__ float g_kvp[(size_t)Bz * Hh * NC * HD * HD];
__device__ float g_kv [(size_t)Bz * Hh * HD * HD]; // (1/pi) * k_hat^T v

__device__ __forceinline__ float warp_sum(float v) {
    v += __shfl_xor_sync(0xffffffffu, v, 16);
    v += __shfl_xor_sync(0xffffffffu, v, 8);
    v += __shfl_xor_sync(0xffffffffu, v, 4);
    v += __shfl_xor_sync(0xffffffffu, v, 2);
    v += __shfl_xor_sync(0xffffffffu, v, 1);
    return v;
}

// ---- cp.async helpers (base-target safe) ----
__device__ __forceinline__ uint32_t smem_u32(const void* p) {
    uint32_t a;
    asm("{ .reg .u64 t; cvta.to.shared.u64 t, %1; cvt.u32.u64 %0, t; }"
        : "=r"(a) : "l"(p));
    return a;
}
__device__ __forceinline__ void cp16(uint32_t saddr, const void* g) {
    asm volatile("cp.async.cg.shared.global [%0], [%1], 16;"
                 :: "r"(saddr), "l"(g) : "memory");
}
#define CP_COMMIT() asm volatile("cp.async.commit_group;" ::: "memory")
#define CP_WAIT(n)  asm volatile("cp.async.wait_group %0;" :: "n"(n) : "memory")

__device__ __forceinline__ uint32_t cvt_tf32(float f) {
    uint32_t u;
    asm("cvt.rna.tf32.f32 %0, %1;" : "=r"(u) : "f"(f));
    return u;
}
__device__ __forceinline__ void mma_tf32(float* c, const uint32_t* a, const uint32_t* b) {
    asm volatile(
        "mma.sync.aligned.m16n8k8.row.col.f32.tf32.tf32.f32 "
        "{%0,%1,%2,%3}, {%4,%5,%6,%7}, {%8,%9}, {%0,%1,%2,%3};"
        : "+f"(c[0]), "+f"(c[1]), "+f"(c[2]), "+f"(c[3])
        : "r"(a[0]), "r"(a[1]), "r"(a[2]), "r"(a[3]), "r"(b[0]), "r"(b[1]));
}

// ============================================================
// tf32 mma.sync GEMM: C[m,n] = sum_k A[m,k]*W[n,k] + bias[n]
// A:[M,K] rm, W:[N,K] rm. 128x128x32 CTA tile, 8 warps (2x4),
// warp tile 64x32, m16n8k8 fragments loaded via conflict-free LDS.
// ============================================================
#define PITCH   36                        // floats per smem row (32 + 4 pad)
#define A_FL    (128 * PITCH)             // floats per A tile
#define STAGE_F (2 * A_FL)                // floats per stage (A + B)
#define GEMM_SMEM (2 * STAGE_F * 4)       // bytes: 73728

__global__ __launch_bounds__(256, 2)
void gemm_mma(const float* __restrict__ A, const float* __restrict__ W,
              const float* __restrict__ bias, float* __restrict__ C,
              int Ndim, int Kdim) {
    extern __shared__ float smem[];
    const uint32_t sbase = smem_u32(smem);
    const int tid = threadIdx.x, wid = tid >> 5, lane = tid & 31;
    const int wm = wid >> 2, wn = wid & 3;           // warp grid 2x4
    const int n0 = blockIdx.x << 7, m0 = blockIdx.y << 7;
    const int r = lane >> 2, cq = lane & 3;
    const int nch = Kdim >> 5;

    float acc[4][4][4];
    #pragma unroll
    for (int i = 0; i < 4; i++)
        #pragma unroll
        for (int j = 0; j < 4; j++)
            #pragma unroll
            for (int l = 0; l < 4; l++) acc[i][j][l] = 0.f;

    auto load_stage = [&](int k0, int st) {
        const uint32_t base = sbase + (uint32_t)st * (STAGE_F * 4);
        #pragma unroll
        for (int p = 0; p < 4; p++) {
            const int idx = tid + (p << 8);          // 0..1023
            const int row = idx >> 3, seg = idx & 7;
            cp16(base + (uint32_t)(row * (PITCH * 4) + seg * 16),
                 A + (size_t)(m0 + row) * Kdim + k0 + seg * 4);
        }
        #pragma unroll
        for (int p = 0; p < 4; p++) {
            const int idx = tid + (p << 8);
            const int row = idx >> 3, seg = idx & 7;
            cp16(base + (uint32_t)(A_FL * 4) + (uint32_t)(row * (PITCH * 4) + seg * 16),
                 W + (size_t)(n0 + row) * Kdim + k0 + seg * 4);
        }
        CP_COMMIT();
    };

    load_stage(0, 0);

    for (int c = 0; c < nch; c++) {
        if (c + 1 < nch) {
            load_stage((c + 1) << 5, (c + 1) & 1);
            CP_WAIT(1);
        } else {
            CP_WAIT(0);
        }
        __syncthreads();

        const float* sA = smem + (size_t)(c & 1) * STAGE_F;
        const float* sB = sA + A_FL;

        #pragma unroll
        for (int kk = 0; kk < 4; kk++) {
            uint32_t af[4][4], bf[4][2];
            #pragma unroll
            for (int mt = 0; mt < 4; mt++) {
                const float* ap = sA + (wm * 64 + mt * 16 + r) * PITCH + kk * 8 + cq;
                af[mt][0] = cvt_tf32(ap[0]);
                af[mt][1] = cvt_tf32(ap[8 * PITCH]);
                af[mt][2] = cvt_tf32(ap[4]);
                af[mt][3] = cvt_tf32(ap[8 * PITCH + 4]);
            }
            #pragma unroll
            for (int nt = 0; nt < 4; nt++) {
                const float* bp = sB + (wn * 32 + nt * 8 + r) * PITCH + kk * 8 + cq;
                bf[nt][0] = cvt_tf32(bp[0]);
                bf[nt][1] = cvt_tf32(bp[4]);
            }
            #pragma unroll
            for (int mt = 0; mt < 4; mt++)
                #pragma unroll
                for (int nt = 0; nt < 4; nt++)
                    mma_tf32(acc[mt][nt], af[mt], bf[nt]);
        }
        __syncthreads();
    }

    // epilogue: acc -> C (+bias). c0:(r,2c) c1:(r,2c+1) c2:(r+8,2c) c3:(r+8,2c+1)
    #pragma unroll
    for (int mt = 0; mt < 4; mt++) {
        const int row0 = m0 + wm * 64 + mt * 16 + r;
        #pragma unroll
        for (int nt = 0; nt < 4; nt++) {
            const int col = n0 + wn * 32 + nt * 8 + cq * 2;
            const float b0 = bias[col], b1 = bias[col + 1];
            *(float2*)&C[(size_t)row0 * Ndim + col] =
                make_float2(acc[mt][nt][0] + b0, acc[mt][nt][1] + b1);
            *(float2*)&C[(size_t)(row0 + 8) * Ndim + col] =
                make_float2(acc[mt][nt][2] + b0, acc[mt][nt][3] + b1);
        }
    }
}

// ============================================================
// kv partials: for (b,h,chunk): acc[dd][ee] = sum_{s in chunk} khat[s,dd]*v[s,ee]
// ============================================================
__global__ __launch_bounds__(256)
void kv_partial(float* __restrict__ kvp) {
    const int bh    = blockIdx.x;          // 0..191
    const int chunk = blockIdx.y;          // 0..3
    const int b = bh / Hh, h = bh % Hh;
    __shared__ float kh[8][64];
    __shared__ float vr[8][64];
    const int tid  = threadIdx.x;
    const int w    = tid >> 5, lane = tid & 31;
    const int tr4  = (tid >> 4) * 4;       // dd base
    const int tc4  = (tid & 15) * 4;       // ee base

    float acc[4][4];
    #pragma unroll
    for (int i = 0; i < 4; i++)
        #pragma unroll
        for (int j = 0; j < 4; j++) acc[i][j] = 0.f;

    for (int t = 0; t < CS / 8; t++) {
        const int s = chunk * CS + t * 8 + w;
        const size_t base = (size_t)(b * Sz + s) * E3 + h * HD;
        float k0 = g_qkv[base + Dz + lane];
        float k1 = g_qkv[base + Dz + 32 + lane];
        float v0 = g_qkv[base + 2 * Dz + lane];
        float v1 = g_qkv[base + 2 * Dz + 32 + lane];
        float nk = warp_sum(k0 * k0 + k1 * k1);
        float rk = rsqrtf(nk);
        kh[w][lane]      = k0 * rk;
        kh[w][lane + 32] = k1 * rk;
        vr[w][lane]      = v0;
        vr[w][lane + 32] = v1;
        __syncthreads();
        #pragma unroll
        for (int s8 = 0; s8 < 8; s8++) {
            float4 kk = *(const float4*)&kh[s8][tr4];
            float4 vv = *(const float4*)&vr[s8][tc4];
            const float kkv[4] = {kk.x, kk.y, kk.z, kk.w};
            const float vvv[4] = {vv.x, vv.y, vv.z, vv.w};
            #pragma unroll
            for (int i = 0; i < 4; i++)
                #pragma unroll
                for (int j = 0; j < 4; j++)
                    acc[i][j] += kkv[i] * vvv[j];
        }
        __syncthreads();
    }
    const size_t pbase = ((size_t)bh * NC + chunk) * (HD * HD);
    #pragma unroll
    for (int i = 0; i < 4; i++) {
        float4 o = make_float4(acc[i][0], acc[i][1], acc[i][2], acc[i][3]);
        *(float4*)&kvp[pbase + (size_t)(tr4 + i) * HD + tc4] = o;
    }
}

__global__ void kv_reduce(const float* __restrict__ kvp, float* __restrict__ kv) {
    const int bh = blockIdx.x;
    const float inv_pi = 0.31830988618379067f;
    for (int i = threadIdx.x; i < HD * HD; i += blockDim.x) {
        float s = 0.f;
        #pragma unroll
        for (int c = 0; c < NC; c++)
            s += kvp[((size_t)bh * NC + c) * (HD * HD) + i];
        kv[(size_t)bh * (HD * HD) + i] = s * inv_pi;
    }
}

// ============================================================
// Fused: out = normalize(0.5*v + qhat @ kv) + dconv(v), write to g_mid
// ============================================================
__global__ __launch_bounds__(256)
void attn_out(const float* __restrict__ kv, const float* __restrict__ wd) {
    __shared__ float kvs[64 * 64];
    __shared__ float vt[72 * 64];   // rows s0-4 .. s0+67
    __shared__ float qs[8][64];
    __shared__ float wds[9];
    const int b = blockIdx.z, h = blockIdx.y;
    const int s0 = blockIdx.x * 64;
    const int tid = threadIdx.x, w = tid >> 5, lane = tid & 31;
    const int bh = b * Hh + h;

    if (tid < 9) wds[tid] = wd[h * 9 + tid];
    for (int i = tid * 4; i < 64 * 64; i += 1024)
        *(float4*)&kvs[i] = *(const float4*)&kv[(size_t)bh * 4096 + i];
    for (int idx = tid; idx < 72 * 64; idx += 256) {
        const int r = idx >> 6, c = idx & 63;
        const int s = s0 - 4 + r;
        vt[idx] = (s >= 0 && s < Sz)
                ? g_qkv[(size_t)(b * Sz + s) * E3 + 2 * Dz + h * HD + c] : 0.f;
    }
    __syncthreads();

    for (int i = 0; i < 8; i++) {
        const int s = s0 + w * 8 + i;
        const size_t base = (size_t)(b * Sz + s) * E3 + h * HD;
        float2 q2 = *(const float2*)&g_qkv[base + 2 * lane];
        float rq = rsqrtf(warp_sum(q2.x * q2.x + q2.y * q2.y));
        *(float2*)&qs[w][2 * lane] = make_float2(q2.x * rq, q2.y * rq);
        __syncwarp();
        float ax = 0.f, ay = 0.f;
        #pragma unroll 8
        for (int e = 0; e < 64; e++) {
            const float qe = qs[w][e];
            float2 kk = *(const float2*)&kvs[e * 64 + 2 * lane];
            ax += qe * kk.x;
            ay += qe * kk.y;
        }
        __syncwarp();
        const int r = (s - s0) + 4;
        float2 vv = *(const float2*)&vt[r * 64 + 2 * lane];
        float ox = 0.5f * vv.x + ax;   // kv already has 1/pi folded in
        float oy = 0.5f * vv.y + ay;
        float ro = rsqrtf(warp_sum(ox * ox + oy * oy));
        ox *= ro; oy *= ro;
        float dcx = 0.f, dcy = 0.f;
        #pragma unroll
        for (int j = 0; j < 9; j++) {
            float2 vj = *(const float2*)&vt[(s - s0 + j) * 64 + 2 * lane];
            dcx += wds[j] * vj.x;
            dcy += wds[j] * vj.y;
        }
        *(float2*)&g_mid[(size_t)(b * Sz + s) * Dz + h * HD + 2 * lane] =
            make_float2(ox + dcx, oy + dcy);
    }
}

// ============================================================
extern "C" void kernel_launch(void* const* d_in, const int* in_sizes, int n_in,
                              void* d_out, int out_size) {
    const float* x      = (const float*)d_in[0];
    const float* w_qkv  = (const float*)d_in[1];
    const float* b_qkv  = (const float*)d_in[2];
    const float* w_proj = (const float*)d_in[3];
    const float* b_proj = (const float*)d_in[4];
    const float* w_dcv  = (const float*)d_in[5];
    float* out = (float*)d_out;

    void *p_qkv, *p_mid, *p_kvp, *p_kv;
    cudaGetSymbolAddress(&p_qkv, g_qkv);
    cudaGetSymbolAddress(&p_mid, g_mid);
    cudaGetSymbolAddress(&p_kvp, g_kvp);
    cudaGetSymbolAddress(&p_kv,  g_kv);

    cudaFuncSetAttribute(gemm_mma, cudaFuncAttributeMaxDynamicSharedMemorySize, GEMM_SMEM);

    // 1) qkv = x @ w_qkv^T + b_qkv   (tf32 mma.sync)
    gemm_mma<<<dim3(E3 / 128, Mrow / 128), 256, GEMM_SMEM>>>(
        x, w_qkv, b_qkv, (float*)p_qkv, E3, Dz);
    // 2) kv partials + reduce (scales by 1/pi)
    kv_partial<<<dim3(Bz * Hh, NC), 256>>>((float*)p_kvp);
    kv_reduce<<<Bz * Hh, 256>>>((const float*)p_kvp, (float*)p_kv);
    // 3) fused attention epilogue -> g_mid
    attn_out<<<dim3(Sz / 64, Hh, Bz), 256>>>((const float*)p_kv, w_dcv);
    // 4) final projection (tf32 mma.sync)
    gemm_mma<<<dim3(Dz / 128, Mrow / 128), 256, GEMM_SMEM>>>(
        (const float*)p_mid, w_proj, b_proj, out, Dz, Dz);
}

// round 7
// speedup vs baseline: 4.0789x; 1.4795x over previous
#include <cuda_runtime.h>
#include <cuda_fp16.h>
#include <cstdint>

#define Bz   16
#define Sz   4096
#define Dz   768
#define Hh   12
#define HD   64
#define E3   2304          // 3*Dz
#define Mrow (Bz*Sz)       // 65536
#define NC   4             // S-chunks for kv partial
#define CS   (Sz/NC)       // 1024

// -------- scratch (device globals: allocation-free) --------
__device__ float  g_qkv[(size_t)Mrow * E3];     // fp32 qkv activations
__device__ float  g_kvp[(size_t)Bz * Hh * NC * HD * HD];
__device__ float  g_kv [(size_t)Bz * Hh * HD * HD];
__device__ __half g_xh  [(size_t)Mrow * Dz];    // fp16 copy of x
__device__ __half g_wqh [(size_t)E3 * Dz];      // fp16 w_qkv
__device__ __half g_wph [(size_t)Dz * Dz];      // fp16 w_proj
__device__ __half g_midh[(size_t)Mrow * Dz];    // fp16 pre-projection acts

__device__ __forceinline__ float warp_sum(float v) {
    v += __shfl_xor_sync(0xffffffffu, v, 16);
    v += __shfl_xor_sync(0xffffffffu, v, 8);
    v += __shfl_xor_sync(0xffffffffu, v, 4);
    v += __shfl_xor_sync(0xffffffffu, v, 2);
    v += __shfl_xor_sync(0xffffffffu, v, 1);
    return v;
}

// ---- helpers ----
__device__ __forceinline__ uint32_t smem_u32(const void* p) {
    uint32_t a;
    asm("{ .reg .u64 t; cvta.to.shared.u64 t, %1; cvt.u32.u64 %0, t; }"
        : "=r"(a) : "l"(p));
    return a;
}
__device__ __forceinline__ void cp16(uint32_t saddr, const void* g) {
    asm volatile("cp.async.cg.shared.global [%0], [%1], 16;"
                 :: "r"(saddr), "l"(g) : "memory");
}
#define CP_COMMIT() asm volatile("cp.async.commit_group;" ::: "memory")
#define CP_WAIT(n)  asm volatile("cp.async.wait_group %0;" :: "n"(n) : "memory")

__device__ __forceinline__ uint32_t cvt_tf32(float f) {
    uint32_t u;
    asm("cvt.rna.tf32.f32 %0, %1;" : "=r"(u) : "f"(f));
    return u;
}
__device__ __forceinline__ void mma_tf32(float* c, const uint32_t* a, const uint32_t* b) {
    asm volatile(
        "mma.sync.aligned.m16n8k8.row.col.f32.tf32.tf32.f32 "
        "{%0,%1,%2,%3}, {%4,%5,%6,%7}, {%8,%9}, {%0,%1,%2,%3};"
        : "+f"(c[0]), "+f"(c[1]), "+f"(c[2]), "+f"(c[3])
        : "r"(a[0]), "r"(a[1]), "r"(a[2]), "r"(a[3]), "r"(b[0]), "r"(b[1]));
}
__device__ __forceinline__ void mma_f16(float* c, const uint32_t* a, const uint32_t* b) {
    asm volatile(
        "mma.sync.aligned.m16n8k16.row.col.f32.f16.f16.f32 "
        "{%0,%1,%2,%3}, {%4,%5,%6,%7}, {%8,%9}, {%0,%1,%2,%3};"
        : "+f"(c[0]), "+f"(c[1]), "+f"(c[2]), "+f"(c[3])
        : "r"(a[0]), "r"(a[1]), "r"(a[2]), "r"(a[3]), "r"(b[0]), "r"(b[1]));
}

// ============================================================
// fp32 -> fp16 convert (vectorized x4)
// ============================================================
__global__ void cvt_h(const float4* __restrict__ src, uint2* __restrict__ dst, int n4) {
    int i = blockIdx.x * blockDim.x + threadIdx.x;
    if (i < n4) {
        float4 v = src[i];
        __half2 h0 = __floats2half2_rn(v.x, v.y);
        __half2 h1 = __floats2half2_rn(v.z, v.w);
        dst[i] = make_uint2(*(uint32_t*)&h0, *(uint32_t*)&h1);
    }
}

// ============================================================
// fp16 mma.sync GEMM: C[m,n] = sum_k A[m,k]*W[n,k] + bias[n]
// A:[M,K] fp16 rm, W:[N,K] fp16 rm. 128x128x32 CTA tile,
// 8 warps (2x4), warp 64x32, m16n8k16.
// smem pitch 40 halfs (80B) -> conflict-free u32 fragment loads.
// ============================================================
#define HP       40                      // halfs per smem row
#define HTILE    (128 * HP)              // halfs per tile (5120)
#define HSTAGE   (2 * HTILE)             // halfs per stage (A+B)
#define GEMMH_SMEM (2 * HSTAGE * 2)      // bytes: 40960

__global__ __launch_bounds__(256)
void gemm_h(const __half* __restrict__ A, const __half* __restrict__ W,
            const float* __restrict__ bias, float* __restrict__ C,
            int Ndim, int Kdim) {
    extern __shared__ __half hsm[];
    const uint32_t sbase = smem_u32(hsm);
    const int tid = threadIdx.x, wid = tid >> 5, lane = tid & 31;
    const int wm = wid >> 2, wn = wid & 3;           // warp grid 2x4
    const int n0 = blockIdx.x << 7, m0 = blockIdx.y << 7;
    const int r = lane >> 2, cq = lane & 3;
    const int nch = Kdim >> 5;

    float acc[4][4][4];
    #pragma unroll
    for (int i = 0; i < 4; i++)
        #pragma unroll
        for (int j = 0; j < 4; j++)
            #pragma unroll
            for (int l = 0; l < 4; l++) acc[i][j][l] = 0.f;

    auto load_stage = [&](int k0, int st) {
        const uint32_t base = sbase + (uint32_t)st * (HSTAGE * 2);
        #pragma unroll
        for (int p = 0; p < 2; p++) {
            const int idx = tid + (p << 8);          // 0..511
            const int row = idx >> 2, seg = idx & 3;
            cp16(base + (uint32_t)(row * (HP * 2) + seg * 16),
                 A + (size_t)(m0 + row) * Kdim + k0 + seg * 8);
        }
        #pragma unroll
        for (int p = 0; p < 2; p++) {
            const int idx = tid + (p << 8);
            const int row = idx >> 2, seg = idx & 3;
            cp16(base + (uint32_t)(HTILE * 2) + (uint32_t)(row * (HP * 2) + seg * 16),
                 W + (size_t)(n0 + row) * Kdim + k0 + seg * 8);
        }
        CP_COMMIT();
    };

    load_stage(0, 0);

    for (int c = 0; c < nch; c++) {
        if (c + 1 < nch) {
            load_stage((c + 1) << 5, (c + 1) & 1);
            CP_WAIT(1);
        } else {
            CP_WAIT(0);
        }
        __syncthreads();

        const __half* sA = hsm + (size_t)(c & 1) * HSTAGE;
        const __half* sB = sA + HTILE;

        #pragma unroll
        for (int kk = 0; kk < 2; kk++) {
            uint32_t af[4][4], bf[4][2];
            #pragma unroll
            for (int mt = 0; mt < 4; mt++) {
                const __half* ap = sA + (wm * 64 + mt * 16 + r) * HP + kk * 16 + 2 * cq;
                af[mt][0] = *(const uint32_t*)ap;
                af[mt][1] = *(const uint32_t*)(ap + 8 * HP);
                af[mt][2] = *(const uint32_t*)(ap + 8);
                af[mt][3] = *(const uint32_t*)(ap + 8 * HP + 8);
            }
            #pragma unroll
            for (int nt = 0; nt < 4; nt++) {
                const __half* bp = sB + (wn * 32 + nt * 8 + r) * HP + kk * 16 + 2 * cq;
                bf[nt][0] = *(const uint32_t*)bp;
                bf[nt][1] = *(const uint32_t*)(bp + 8);
            }
            #pragma unroll
            for (int mt = 0; mt < 4; mt++)
                #pragma unroll
                for (int nt = 0; nt < 4; nt++)
                    mma_f16(acc[mt][nt], af[mt], bf[nt]);
        }
        __syncthreads();
    }

    #pragma unroll
    for (int mt = 0; mt < 4; mt++) {
        const int row0 = m0 + wm * 64 + mt * 16 + r;
        #pragma unroll
        for (int nt = 0; nt < 4; nt++) {
            const int col = n0 + wn * 32 + nt * 8 + cq * 2;
            const float b0 = bias[col], b1 = bias[col + 1];
            *(float2*)&C[(size_t)row0 * Ndim + col] =
                make_float2(acc[mt][nt][0] + b0, acc[mt][nt][1] + b1);
            *(float2*)&C[(size_t)(row0 + 8) * Ndim + col] =
                make_float2(acc[mt][nt][2] + b0, acc[mt][nt][3] + b1);
        }
    }
}

// ============================================================
// kv partials: acc[dd][ee] = sum_{s in chunk} khat[s,dd]*v[s,ee]
// ============================================================
__global__ __launch_bounds__(256)
void kv_partial(float* __restrict__ kvp) {
    const int bh    = blockIdx.x;
    const int chunk = blockIdx.y;
    const int b = bh / Hh, h = bh % Hh;
    __shared__ float kh[8][64];
    __shared__ float vr[8][64];
    const int tid  = threadIdx.x;
    const int w    = tid >> 5, lane = tid & 31;
    const int tr4  = (tid >> 4) * 4;
    const int tc4  = (tid & 15) * 4;

    float acc[4][4];
    #pragma unroll
    for (int i = 0; i < 4; i++)
        #pragma unroll
        for (int j = 0; j < 4; j++) acc[i][j] = 0.f;

    for (int t = 0; t < CS / 8; t++) {
        const int s = chunk * CS + t * 8 + w;
        const size_t base = (size_t)(b * Sz + s) * E3 + h * HD;
        float k0 = g_qkv[base + Dz + lane];
        float k1 = g_qkv[base + Dz + 32 + lane];
        float v0 = g_qkv[base + 2 * Dz + lane];
        float v1 = g_qkv[base + 2 * Dz + 32 + lane];
        float rk = rsqrtf(warp_sum(k0 * k0 + k1 * k1));
        kh[w][lane]      = k0 * rk;
        kh[w][lane + 32] = k1 * rk;
        vr[w][lane]      = v0;
        vr[w][lane + 32] = v1;
        __syncthreads();
        #pragma unroll
        for (int s8 = 0; s8 < 8; s8++) {
            float4 kk = *(const float4*)&kh[s8][tr4];
            float4 vv = *(const float4*)&vr[s8][tc4];
            const float kkv[4] = {kk.x, kk.y, kk.z, kk.w};
            const float vvv[4] = {vv.x, vv.y, vv.z, vv.w};
            #pragma unroll
            for (int i = 0; i < 4; i++)
                #pragma unroll
                for (int j = 0; j < 4; j++)
                    acc[i][j] += kkv[i] * vvv[j];
        }
        __syncthreads();
    }
    const size_t pbase = ((size_t)bh * NC + chunk) * (HD * HD);
    #pragma unroll
    for (int i = 0; i < 4; i++)
        *(float4*)&kvp[pbase + (size_t)(tr4 + i) * HD + tc4] =
            make_float4(acc[i][0], acc[i][1], acc[i][2], acc[i][3]);
}

__global__ void kv_reduce(const float* __restrict__ kvp, float* __restrict__ kv) {
    const int bh = blockIdx.x;
    const float inv_pi = 0.31830988618379067f;
    for (int i = threadIdx.x; i < HD * HD; i += blockDim.x) {
        float s = 0.f;
        #pragma unroll
        for (int c = 0; c < NC; c++)
            s += kvp[((size_t)bh * NC + c) * (HD * HD) + i];
        kv[(size_t)bh * (HD * HD) + i] = s * inv_pi;
    }
}

// ============================================================
// attn_out v2: attn = qhat @ kv via tf32 mma.sync, then
// out = normalize(0.5*v + attn) + dconv(v) -> g_midh (fp16)
// ============================================================
#define QS_OFF   0          // qs[64][68] fp32 (later reused for attn)
#define KVT_OFF  4352       // kvT[64][68]  (kv transposed: [e][d])
#define VT_OFF   8704       // vt[72][64]
#define WDS_OFF  13312      // 9 floats
#define ATTN_SMEM ((13312 + 16) * 4)

__global__ __launch_bounds__(256)
void attn_out(const float* __restrict__ kv, const float* __restrict__ wd) {
    extern __shared__ float sm[];
    float* qs  = sm + QS_OFF;
    float* kvT = sm + KVT_OFF;
    float* vt  = sm + VT_OFF;
    float* wds = sm + WDS_OFF;
    const int b = blockIdx.z, h = blockIdx.y;
    const int s0 = blockIdx.x * 64;
    const int tid = threadIdx.x, w = tid >> 5, lane = tid & 31;
    const int r = lane >> 2, cq = lane & 3;
    const int bh = b * Hh + h;

    // -------- phase A: fill qs (normalized q), kvT, vt --------
    if (tid < 9) wds[tid] = wd[h * 9 + tid];
    for (int i = tid; i < 64 * 64; i += 256) {
        const int d = i >> 6, e = i & 63;
        kvT[e * 68 + d] = kv[(size_t)bh * 4096 + i];
    }
    for (int idx = tid; idx < 72 * 64; idx += 256) {
        const int rr = idx >> 6, c = idx & 63;
        const int s = s0 - 4 + rr;
        vt[idx] = (s >= 0 && s < Sz)
                ? g_qkv[(size_t)(b * Sz + s) * E3 + 2 * Dz + h * HD + c] : 0.f;
    }
    #pragma unroll
    for (int i = 0; i < 8; i++) {
        const int row = w * 8 + i;
        const size_t base = (size_t)(b * Sz + s0 + row) * E3 + h * HD;
        float2 q2 = *(const float2*)&g_qkv[base + 2 * lane];
        float rq = rsqrtf(warp_sum(q2.x * q2.x + q2.y * q2.y));
        *(float2*)&qs[row * 68 + 2 * lane] = make_float2(q2.x * rq, q2.y * rq);
    }
    __syncthreads();

    // -------- phase B: attn[64][64] = qs @ kvT^T (tf32 mma) --------
    const int wm = w >> 1, wn = w & 1;   // 4x2 warp grid (16 rows x 32 cols)
    float acc[4][4];
    #pragma unroll
    for (int i = 0; i < 4; i++)
        #pragma unroll
        for (int j = 0; j < 4; j++) acc[i][j] = 0.f;

    #pragma unroll
    for (int ks = 0; ks < 8; ks++) {
        uint32_t af[4], bf[4][2];
        const float* ap = qs + (wm * 16 + r) * 68 + ks * 8 + cq;
        af[0] = cvt_tf32(ap[0]);
        af[1] = cvt_tf32(ap[8 * 68]);
        af[2] = cvt_tf32(ap[4]);
        af[3] = cvt_tf32(ap[8 * 68 + 4]);
        #pragma unroll
        for (int nt = 0; nt < 4; nt++) {
            const float* bp = kvT + (wn * 32 + nt * 8 + r) * 68 + ks * 8 + cq;
            bf[nt][0] = cvt_tf32(bp[0]);
            bf[nt][1] = cvt_tf32(bp[4]);
        }
        #pragma unroll
        for (int nt = 0; nt < 4; nt++)
            mma_tf32(acc[nt], af, bf[nt]);
    }
    __syncthreads();                       // all reads of qs done
    #pragma unroll
    for (int nt = 0; nt < 4; nt++) {
        const int col = wn * 32 + nt * 8 + 2 * cq;
        *(float2*)&qs[(wm * 16 + r) * 68 + col]       = make_float2(acc[nt][0], acc[nt][1]);
        *(float2*)&qs[(wm * 16 + r + 8) * 68 + col]   = make_float2(acc[nt][2], acc[nt][3]);
    }
    __syncthreads();

    // -------- phase C: residual + normalize + dconv -> fp16 --------
    #pragma unroll
    for (int i = 0; i < 8; i++) {
        const int row = w * 8 + i;
        float2 at = *(const float2*)&qs[row * 68 + 2 * lane];
        float2 vv = *(const float2*)&vt[(row + 4) * 64 + 2 * lane];
        float ox = 0.5f * vv.x + at.x;     // kv has 1/pi folded in
        float oy = 0.5f * vv.y + at.y;
        float ro = rsqrtf(warp_sum(ox * ox + oy * oy));
        ox *= ro; oy *= ro;
        float dcx = 0.f, dcy = 0.f;
        #pragma unroll
        for (int j = 0; j < 9; j++) {
            float2 vj = *(const float2*)&vt[(row + j) * 64 + 2 * lane];
            dcx += wds[j] * vj.x;
            dcy += wds[j] * vj.y;
        }
        __half2 h2 = __floats2half2_rn(ox + dcx, oy + dcy);
        *(uint32_t*)&g_midh[(size_t)(b * Sz + s0 + row) * Dz + h * HD + 2 * lane] =
            *(uint32_t*)&h2;
    }
}

// ============================================================
extern "C" void kernel_launch(void* const* d_in, const int* in_sizes, int n_in,
                              void* d_out, int out_size) {
    const float* x      = (const float*)d_in[0];
    const float* w_qkv  = (const float*)d_in[1];
    const float* b_qkv  = (const float*)d_in[2];
    const float* w_proj = (const float*)d_in[3];
    const float* b_proj = (const float*)d_in[4];
    const float* w_dcv  = (const float*)d_in[5];
    float* out = (float*)d_out;

    void *p_qkv, *p_kvp, *p_kv, *p_xh, *p_wqh, *p_wph, *p_midh;
    cudaGetSymbolAddress(&p_qkv, g_qkv);
    cudaGetSymbolAddress(&p_kvp, g_kvp);
    cudaGetSymbolAddress(&p_kv,  g_kv);
    cudaGetSymbolAddress(&p_xh,  g_xh);
    cudaGetSymbolAddress(&p_wqh, g_wqh);
    cudaGetSymbolAddress(&p_wph, g_wph);
    cudaGetSymbolAddress(&p_midh, g_midh);

    cudaFuncSetAttribute(gemm_h,  cudaFuncAttributeMaxDynamicSharedMemorySize, GEMMH_SMEM);
    cudaFuncSetAttribute(attn_out, cudaFuncAttributeMaxDynamicSharedMemorySize, ATTN_SMEM);

    // 0) fp16 converts
    cvt_h<<<(Mrow * Dz / 4 + 255) / 256, 256>>>((const float4*)x, (uint2*)p_xh, Mrow * Dz / 4);
    cvt_h<<<(E3 * Dz / 4 + 255) / 256, 256>>>((const float4*)w_qkv, (uint2*)p_wqh, E3 * Dz / 4);
    cvt_h<<<(Dz * Dz / 4 + 255) / 256, 256>>>((const float4*)w_proj, (uint2*)p_wph, Dz * Dz / 4);

    // 1) qkv = x @ w_qkv^T + b_qkv   (fp16 mma.sync, fp32 out)
    gemm_h<<<dim3(E3 / 128, Mrow / 128), 256, GEMMH_SMEM>>>(
        (const __half*)p_xh, (const __half*)p_wqh, b_qkv, (float*)p_qkv, E3, Dz);
    // 2) kv partials + reduce (scales by 1/pi)
    kv_partial<<<dim3(Bz * Hh, NC), 256>>>((float*)p_kvp);
    kv_reduce<<<Bz * Hh, 256>>>((const float*)p_kvp, (float*)p_kv);
    // 3) fused attention epilogue -> g_midh (fp16)
    attn_out<<<dim3(Sz / 64, Hh, Bz), 256, ATTN_SMEM>>>((const float*)p_kv, w_dcv);
    // 4) final projection (fp16 mma.sync)
    gemm_h<<<dim3(Dz / 128, Mrow / 128), 256, GEMMH_SMEM>>>(
        (const __half*)p_midh, (const __half*)p_wph, b_proj, out, Dz, Dz);
}